// round 3
// baseline (speedup 1.0000x reference)
#include <cuda_runtime.h>
#include <cstdint>

// CSR SpMM, sum-reduce: out[r,:] = sum_{e in row r} value[e] * other[col[e],:]
// N_ROWS=100000, DEG=16 (fixed), F=64, fp32. rowptr/col are INT32 (JAX default x64-disabled).
//
// Layout: 16 threads per row, each owning one float4 (4 features).
// blockDim = (16, 16) -> 256 threads, 16 rows per block.
// Each edge gather: 16 lanes x 16B = one contiguous 256B row of `other` (8 sectors, perfect).
// col/value loads broadcast within the 16-lane group. Fixed degree 16 ->
// index/value pre-pass then 16 front-batched independent float4 gathers (MLP=16)
// to hide L2 latency (~250 cyc); `other` (25.6MB) fits in the 126MB L2.

static constexpr int F4 = 16;       // float4 groups per row (F=64)
static constexpr int ROWS_PER_BLK = 16;

__global__ __launch_bounds__(256) void spmm_kernel(
    const int* __restrict__ rowptr,
    const int* __restrict__ col,
    const float* __restrict__ value,
    const float4* __restrict__ other,   // [N_COLS * 16] float4
    float4* __restrict__ out,           // [N_ROWS * 16] float4
    int n_rows)
{
    const int row = blockIdx.x * ROWS_PER_BLK + threadIdx.y;
    if (row >= n_rows) return;
    const int f = threadIdx.x;          // 0..15

    const int start = rowptr[row];
    const int deg   = rowptr[row + 1] - start;

    float4 acc = make_float4(0.f, 0.f, 0.f, 0.f);

    if (deg == 16) {
        // Pre-load all indices/values, then issue 16 independent gathers.
        int   c[16];
        float v[16];
#pragma unroll
        for (int k = 0; k < 16; ++k) {
            c[k] = __ldg(&col[start + k]);
            v[k] = __ldg(&value[start + k]);
        }
#pragma unroll
        for (int k = 0; k < 16; ++k) {
            const float4 x = __ldg(&other[(long long)c[k] * F4 + f]);
            acc.x = fmaf(v[k], x.x, acc.x);
            acc.y = fmaf(v[k], x.y, acc.y);
            acc.z = fmaf(v[k], x.z, acc.z);
            acc.w = fmaf(v[k], x.w, acc.w);
        }
    } else {
        for (int e = start; e < start + deg; ++e) {
            const int   c = __ldg(&col[e]);
            const float v = __ldg(&value[e]);
            const float4 x = __ldg(&other[(long long)c * F4 + f]);
            acc.x = fmaf(v, x.x, acc.x);
            acc.y = fmaf(v, x.y, acc.y);
            acc.z = fmaf(v, x.z, acc.z);
            acc.w = fmaf(v, x.w, acc.w);
        }
    }

    out[(long long)row * F4 + f] = acc;
}

extern "C" void kernel_launch(void* const* d_in, const int* in_sizes, int n_in,
                              void* d_out, int out_size)
{
    // metadata order: rowptr (int32, N_ROWS+1), col (int32, E), value (f32, E), other (f32, N_COLS*F)
    const int*    rowptr = (const int*)d_in[0];
    const int*    col    = (const int*)d_in[1];
    const float*  value  = (const float*)d_in[2];
    const float4* other  = (const float4*)d_in[3];
    float4*       out    = (float4*)d_out;

    const int n_rows = in_sizes[0] - 1;

    dim3 block(F4, ROWS_PER_BLK);
    dim3 grid((n_rows + ROWS_PER_BLK - 1) / ROWS_PER_BLK);
    spmm_kernel<<<grid, block>>>(rowptr, col, value, other, out, n_rows);
}